// round 11
// baseline (speedup 1.0000x reference)
#include <cuda_runtime.h>
#include <cuda_fp16.h>
#include <mma.h>

using namespace nvcuda;

#define MAX_NODES 100000
#define MAX_EDGES 1600000
#define D 64
#define MAX_FEAT (MAX_NODES * D)
#define PAD 16384                 // rows past n touched by full wmma tiles
#define CAP 64                    // slots per node; P(Poisson(16) > 64) ~ 1e-20
#define MAX_SPILL 8192
#define M_BLK 128                 // nodes per fused block (8 warps x 16 rows)

// Static scratch (no runtime allocation allowed)
__device__ __align__(16) __half g_fts16[MAX_FEAT + PAD];   // 12.8 MB fp16 fts
__device__ __align__(16) __half g_W16[128 * D];            // 16 KB  fp16 W
__device__ int g_slots[MAX_NODES * CAP];                   // 25.6 MB
__device__ int g_deg[MAX_NODES];
__device__ int g_spill[2 * MAX_SPILL];
__device__ int g_nspill;
__device__ int g_is64;

// ---------------------------------------------------------------------------
// K0: convert fts -> fp16 and W -> fp16, zero degrees/pad rows/spill counter;
// block 0 detects edge_index dtype (int64 => odd int32 words all zero;
// int32 => odd words are random node ids, 4096 all-zero samples impossible).
// ---------------------------------------------------------------------------
__global__ void init_kernel(const float* __restrict__ fts,
                            const float* __restrict__ W,
                            const int* __restrict__ ei32, int E, int n) {
    int i = blockIdx.x * blockDim.x + threadIdx.x;
    int n8 = n * (D / 8);                 // groups of 8 floats
    if (i < n8) {
        const float4* s = reinterpret_cast<const float4*>(fts) + i * 2;
        float4 a = s[0], b = s[1];
        __half2 h0 = __floats2half2_rn(a.x, a.y);
        __half2 h1 = __floats2half2_rn(a.z, a.w);
        __half2 h2 = __floats2half2_rn(b.x, b.y);
        __half2 h3 = __floats2half2_rn(b.z, b.w);
        uint4 pack;
        pack.x = *reinterpret_cast<unsigned*>(&h0);
        pack.y = *reinterpret_cast<unsigned*>(&h1);
        pack.z = *reinterpret_cast<unsigned*>(&h2);
        pack.w = *reinterpret_cast<unsigned*>(&h3);
        reinterpret_cast<uint4*>(g_fts16)[i] = pack;
    }
    if (i < PAD / 8) {
        uint4 z = make_uint4(0u, 0u, 0u, 0u);
        reinterpret_cast<uint4*>(g_fts16 + MAX_FEAT)[i] = z;
    }
    if (i < 1024) {                       // W: 8192 floats
        const float4* s = reinterpret_cast<const float4*>(W) + i * 2;
        float4 a = s[0], b = s[1];
        __half2 h0 = __floats2half2_rn(a.x, a.y);
        __half2 h1 = __floats2half2_rn(a.z, a.w);
        __half2 h2 = __floats2half2_rn(b.x, b.y);
        __half2 h3 = __floats2half2_rn(b.z, b.w);
        uint4 pack;
        pack.x = *reinterpret_cast<unsigned*>(&h0);
        pack.y = *reinterpret_cast<unsigned*>(&h1);
        pack.z = *reinterpret_cast<unsigned*>(&h2);
        pack.w = *reinterpret_cast<unsigned*>(&h3);
        reinterpret_cast<uint4*>(g_W16)[i] = pack;
    }
    if (i < n) g_deg[i] = 0;
    if (i == 0) g_nspill = 0;
    if (blockIdx.x == 0) {
        __shared__ int any_nonzero;
        if (threadIdx.x == 0) any_nonzero = 0;
        __syncthreads();
        long long total = 2LL * E;
        long long stride = total / 4096;
        if (stride < 2) stride = 2;
        for (int s = threadIdx.x; s < 4096; s += blockDim.x) {
            long long idx = ((long long)s * stride) | 1;
            if (idx < total && ei32[idx] != 0) any_nonzero = 1;
        }
        __syncthreads();
        if (threadIdx.x == 0) g_is64 = any_nonzero ? 0 : 1;
    }
}

__device__ __forceinline__ void load_edge(const void* ei_raw, int E, int e,
                                          int& u, int& v) {
    if (g_is64) {
        const long long* ei = (const long long*)ei_raw;
        u = (int)ei[e];
        v = (int)ei[E + e];
    } else {
        const int* ei = (const int*)ei_raw;
        u = ei[e];
        v = ei[E + e];
    }
}

// ---------------------------------------------------------------------------
// K1: single-pass bucket fill (CSR without scan).
// ---------------------------------------------------------------------------
__global__ void fill_slots_kernel(const void* __restrict__ ei_raw, int E, int n) {
    int e = blockIdx.x * blockDim.x + threadIdx.x;
    if (e >= E) return;
    int u, v;
    load_edge(ei_raw, E, e, u, v);
    if ((unsigned)u >= (unsigned)n || (unsigned)v >= (unsigned)n) return;
    int idx = atomicAdd(&g_deg[u], 1);
    if (idx < CAP) {
        g_slots[u * CAP + idx] = v;
    } else {
        int p = atomicAdd(&g_nspill, 1);
        if (p < MAX_SPILL) { g_spill[2 * p] = u; g_spill[2 * p + 1] = v; }
    }
}

// ---------------------------------------------------------------------------
// K2: FUSED aggregation + spill + tensor-core GEMM + L2 norm.
// Block = 256 threads = 8 warps, covers 128 nodes.
//  Phase 1: fp16 max-aggregation of this block's 128 nodes into SMEM
//           (2 threads per node, 32 cols each, __hmax2, unroll x2 => 8
//           independent 16B loads in flight). Init at 0 = ReLU + empties.
//  Phase 2: merge spill-list entries touching this block (empty in practice;
//           single guarded loop, skipped when g_nspill == 0).
//  Phase 3: wmma m16n16k16 GEMM; A cols 0-63 from g_fts16 (global),
//           cols 64-127 from the SMEM agg tile. fp32 accumulate + row norm.
// ---------------------------------------------------------------------------
__global__ __launch_bounds__(256) void fused_kernel(float* __restrict__ out,
                                                    int n) {
    __shared__ __align__(16) __half sAgg[M_BLK * D];   // 16 KB
    __shared__ float Cs[8 * 16 * 64];                  // 32 KB

    int t = threadIdx.x;
    int blockBase = blockIdx.x * M_BLK;

    // ---- Phase 1: aggregate 128 nodes into sAgg ----
    {
        int nl = t >> 1;                   // local node 0..127
        int h = t & 1;                     // column half: 32 cols
        int node = blockBase + nl;

        __half2 m[4];
#pragma unroll
        for (int j = 0; j < 4; ++j) {
            __half2 z = __float2half2_rn(0.f);
            m[j] = z;                      // placeholder; widened below
        }
        // 32 cols = 4 uint4 = 16 half2; keep as 4 uint4-sized register groups
        __half2 mm[16];
#pragma unroll
        for (int j = 0; j < 16; ++j) mm[j] = __float2half2_rn(0.f);

        if (node < n) {
            int deg = g_deg[node];
            if (deg > CAP) deg = CAP;
            const int* vs = g_slots + node * CAP;
            const uint4* f16 = reinterpret_cast<const uint4*>(g_fts16);
            int base4 = h * 4;             // uint4 index within row (0 or 4)

            int i = 0;
            for (; i + 2 <= deg; i += 2) {
                int v0 = vs[i], v1 = vs[i + 1];
                uint4 q[8];
#pragma unroll
                for (int j = 0; j < 4; ++j) q[j]     = f16[v0 * 8 + base4 + j];
#pragma unroll
                for (int j = 0; j < 4; ++j) q[4 + j] = f16[v1 * 8 + base4 + j];
#pragma unroll
                for (int j = 0; j < 8; ++j) {
                    const __half2* p = reinterpret_cast<const __half2*>(&q[j]);
                    int o = (j & 3) * 4;
                    mm[o + 0] = __hmax2(mm[o + 0], p[0]);
                    mm[o + 1] = __hmax2(mm[o + 1], p[1]);
                    mm[o + 2] = __hmax2(mm[o + 2], p[2]);
                    mm[o + 3] = __hmax2(mm[o + 3], p[3]);
                }
            }
            for (; i < deg; ++i) {
                int v = vs[i];
#pragma unroll
                for (int j = 0; j < 4; ++j) {
                    uint4 q = f16[v * 8 + base4 + j];
                    const __half2* p = reinterpret_cast<const __half2*>(&q);
                    mm[j * 4 + 0] = __hmax2(mm[j * 4 + 0], p[0]);
                    mm[j * 4 + 1] = __hmax2(mm[j * 4 + 1], p[1]);
                    mm[j * 4 + 2] = __hmax2(mm[j * 4 + 2], p[2]);
                    mm[j * 4 + 3] = __hmax2(mm[j * 4 + 3], p[3]);
                }
            }
        }
        // write 32 cols to smem (zeros for node >= n)
        uint4* dst = reinterpret_cast<uint4*>(sAgg + nl * D + h * 32);
#pragma unroll
        for (int j = 0; j < 4; ++j) {
            uint4 pack;
            pack.x = *reinterpret_cast<unsigned*>(&mm[j * 4 + 0]);
            pack.y = *reinterpret_cast<unsigned*>(&mm[j * 4 + 1]);
            pack.z = *reinterpret_cast<unsigned*>(&mm[j * 4 + 2]);
            pack.w = *reinterpret_cast<unsigned*>(&mm[j * 4 + 3]);
            dst[j] = pack;
        }
    }
    __syncthreads();

    // ---- Phase 2: spill merge (expected empty) ----
    if (t == 0) {
        int ns = g_nspill;
        if (ns > MAX_SPILL) ns = MAX_SPILL;
        for (int e = 0; e < ns; ++e) {
            int u = g_spill[2 * e];
            if (u >= blockBase && u < blockBase + M_BLK && u < n) {
                int v = g_spill[2 * e + 1];
                __half2 zero = __float2half2_rn(0.f);
                const __half2* src =
                    reinterpret_cast<const __half2*>(g_fts16 + (size_t)v * D);
                __half2* dst =
                    reinterpret_cast<__half2*>(sAgg + (u - blockBase) * D);
                for (int c = 0; c < 32; ++c)
                    dst[c] = __hmax2(dst[c], __hmax2(zero, src[c]));
            }
        }
    }
    __syncthreads();

    // ---- Phase 3: wmma GEMM + L2 norm ----
    int warp = t >> 5;
    int lane = t & 31;
    int row0 = blockBase + warp * 16;

    wmma::fragment<wmma::accumulator, 16, 16, 16, float> c[4];
#pragma unroll
    for (int nn = 0; nn < 4; ++nn) wmma::fill_fragment(c[nn], 0.f);

#pragma unroll
    for (int kc = 0; kc < 8; ++kc) {
        wmma::fragment<wmma::matrix_a, 16, 16, 16, __half, wmma::row_major> a;
        if (kc < 4) {
            wmma::load_matrix_sync(a, g_fts16 + (size_t)row0 * D + kc * 16, D);
        } else {
            wmma::load_matrix_sync(a, sAgg + (warp * 16) * D + (kc - 4) * 16, D);
        }
#pragma unroll
        for (int nn = 0; nn < 4; ++nn) {
            wmma::fragment<wmma::matrix_b, 16, 16, 16, __half, wmma::row_major> b;
            wmma::load_matrix_sync(b, g_W16 + (size_t)(kc * 16) * D + nn * 16, D);
            wmma::mma_sync(c[nn], a, b, c[nn]);
        }
    }

    float* cs = Cs + warp * 16 * 64;
#pragma unroll
    for (int nn = 0; nn < 4; ++nn)
        wmma::store_matrix_sync(cs + nn * 16, c[nn], 64, wmma::mem_row_major);
    __syncwarp();

    int r = lane >> 1;
    int ch = (lane & 1) * 32;
    const float* rowp = cs + r * 64 + ch;
    float v[32];
    float ss = 0.f;
#pragma unroll
    for (int j = 0; j < 32; ++j) {
        v[j] = rowp[j];
        ss = fmaf(v[j], v[j], ss);
    }
    ss += __shfl_xor_sync(0xffffffffu, ss, 1);
    float rn = rsqrtf(ss);

    int grow = row0 + r;
    if (grow < n) {
        float4* o = reinterpret_cast<float4*>(out + (size_t)grow * D + ch);
#pragma unroll
        for (int j = 0; j < 8; ++j) {
            float4 q;
            q.x = v[4 * j + 0] * rn;
            q.y = v[4 * j + 1] * rn;
            q.z = v[4 * j + 2] * rn;
            q.w = v[4 * j + 3] * rn;
            o[j] = q;
        }
    }
}

// ---------------------------------------------------------------------------
// Launch: 3 kernels total (launch overhead in this harness is ~4us each).
// Inputs identified by ELEMENT COUNT (robust to metadata order).
// ---------------------------------------------------------------------------
extern "C" void kernel_launch(void* const* d_in, const int* in_sizes, int n_in,
                              void* d_out, int out_size) {
    const float* fts = 0;
    const void*  ei  = 0;
    const float* W   = 0;
    int n = MAX_NODES, E = MAX_EDGES;

    for (int i = 0; i < n_in; ++i) {
        if (in_sizes[i] == 6400000)      { fts = (const float*)d_in[i]; n = in_sizes[i] / D; }
        else if (in_sizes[i] == 3200000) { ei  = d_in[i]; E = in_sizes[i] / 2; }
        else if (in_sizes[i] == 8192)    { W   = (const float*)d_in[i]; }
    }
    float* out = (float*)d_out;

    int n8 = n * (D / 8);
    init_kernel<<<(n8 + 255) / 256, 256>>>(fts, W, (const int*)ei, E, n);
    fill_slots_kernel<<<(E + 255) / 256, 256>>>(ei, E, n);
    fused_kernel<<<(n + M_BLK - 1) / M_BLK, 256>>>(out, n);
}

// round 12
// speedup vs baseline: 1.0913x; 1.0913x over previous
#include <cuda_runtime.h>
#include <cuda_fp16.h>
#include <mma.h>

using namespace nvcuda;

#define MAX_NODES 100000
#define MAX_EDGES 1600000
#define D 64
#define MAX_FEAT (MAX_NODES * D)
#define PAD 16384                 // rows past n touched by full wmma tiles
#define CAP 64                    // slots per node; P(Poisson(16) > 64) ~ 1e-20
#define MAX_SPILL 8192
#define M_BLK 128                 // rows per GEMM block (8 warps x 16)

// Static scratch (no runtime allocation allowed)
__device__ __align__(16) __half g_fts16[MAX_FEAT + PAD];   // 12.8 MB fp16 fts
__device__ __align__(16) __half g_agg16[MAX_FEAT + PAD];   // 12.8 MB fp16 agg
__device__ __align__(16) __half g_W16[128 * D];            // 16 KB  fp16 W
__device__ int g_slots[MAX_NODES * CAP];                   // 25.6 MB
__device__ int g_deg[MAX_NODES];
__device__ int g_spill[2 * MAX_SPILL];
__device__ int g_nspill;
__device__ int g_is64;

__device__ __forceinline__ uint4 cvt8(const float4* s) {
    float4 a = s[0], b = s[1];
    __half2 h0 = __floats2half2_rn(a.x, a.y);
    __half2 h1 = __floats2half2_rn(a.z, a.w);
    __half2 h2 = __floats2half2_rn(b.x, b.y);
    __half2 h3 = __floats2half2_rn(b.z, b.w);
    uint4 pack;
    pack.x = *reinterpret_cast<unsigned*>(&h0);
    pack.y = *reinterpret_cast<unsigned*>(&h1);
    pack.z = *reinterpret_cast<unsigned*>(&h2);
    pack.w = *reinterpret_cast<unsigned*>(&h3);
    return pack;
}

// ---------------------------------------------------------------------------
// K0: convert fts -> fp16 (16 floats per thread => 4 independent LDG.128 in
// flight; the old 8-float version profiled latency-bound at issue=16.6%),
// convert W -> fp16, zero deg/pad/spill; block 0 detects edge_index dtype
// (int64 => odd int32 words all zero; int32 => random ids, never all zero).
// ---------------------------------------------------------------------------
__global__ void init_kernel(const float* __restrict__ fts,
                            const float* __restrict__ W,
                            const int* __restrict__ ei32, int E, int n) {
    int i = blockIdx.x * blockDim.x + threadIdx.x;
    int n16 = n * (D / 16);               // groups of 16 floats (400000)
    if (i < n16) {
        const float4* s = reinterpret_cast<const float4*>(fts) + i * 4;
        uint4 p0 = cvt8(s);
        uint4 p1 = cvt8(s + 2);
        uint4* d = reinterpret_cast<uint4*>(g_fts16) + i * 2;
        d[0] = p0;
        d[1] = p1;
    }
    if (i < PAD / 16) {                   // zero wmma padding rows
        uint4 z = make_uint4(0u, 0u, 0u, 0u);
        uint4* d0 = reinterpret_cast<uint4*>(g_fts16 + MAX_FEAT) + i * 2;
        uint4* d1 = reinterpret_cast<uint4*>(g_agg16 + MAX_FEAT) + i * 2;
        d0[0] = z; d0[1] = z;
        d1[0] = z; d1[1] = z;
    }
    if (i < 512) {                        // W: 8192 floats, 16 per thread
        const float4* s = reinterpret_cast<const float4*>(W) + i * 4;
        uint4 p0 = cvt8(s);
        uint4 p1 = cvt8(s + 2);
        uint4* d = reinterpret_cast<uint4*>(g_W16) + i * 2;
        d[0] = p0;
        d[1] = p1;
    }
    if (i < n) g_deg[i] = 0;
    if (i == 0) g_nspill = 0;
    if (blockIdx.x == 0) {
        __shared__ int any_nonzero;
        if (threadIdx.x == 0) any_nonzero = 0;
        __syncthreads();
        long long total = 2LL * E;
        long long stride = total / 4096;
        if (stride < 2) stride = 2;
        for (int s = threadIdx.x; s < 4096; s += blockDim.x) {
            long long idx = ((long long)s * stride) | 1;
            if (idx < total && ei32[idx] != 0) any_nonzero = 1;
        }
        __syncthreads();
        if (threadIdx.x == 0) g_is64 = any_nonzero ? 0 : 1;
    }
}

__device__ __forceinline__ void load_edge(const void* ei_raw, int E, int e,
                                          int& u, int& v) {
    if (g_is64) {
        const long long* ei = (const long long*)ei_raw;
        u = (int)ei[e];
        v = (int)ei[E + e];
    } else {
        const int* ei = (const int*)ei_raw;
        u = ei[e];
        v = ei[E + e];
    }
}

// ---------------------------------------------------------------------------
// K1: single-pass bucket fill (CSR without scan).
// ---------------------------------------------------------------------------
__global__ void fill_slots_kernel(const void* __restrict__ ei_raw, int E, int n) {
    int e = blockIdx.x * blockDim.x + threadIdx.x;
    if (e >= E) return;
    int u, v;
    load_edge(ei_raw, E, e, u, v);
    if ((unsigned)u >= (unsigned)n || (unsigned)v >= (unsigned)n) return;
    int idx = atomicAdd(&g_deg[u], 1);
    if (idx < CAP) {
        g_slots[u * CAP + idx] = v;
    } else {
        int p = atomicAdd(&g_nspill, 1);
        if (p < MAX_SPILL) { g_spill[2 * p] = u; g_spill[2 * p + 1] = v; }
    }
}

// ---------------------------------------------------------------------------
// K2: aggregation. 8 threads/node (max parallelism, short latency chains —
// the 2-thread/node fused variant regressed), fp16 __hmax2 register max,
// unroll x4 => 8 independent 16B loads in flight. Output fp16 for the HMMA
// GEMM. Init at 0 handles ReLU + empty nodes.
// ---------------------------------------------------------------------------
__global__ __launch_bounds__(256) void agg_kernel(int n) {
    int node = blockIdx.x * 32 + (threadIdx.x >> 3);
    int l8 = threadIdx.x & 7;
    if (node >= n) return;

    __half2 m0 = __float2half2_rn(0.f);
    __half2 m1 = m0, m2 = m0, m3 = m0;

    int deg = g_deg[node];
    if (deg > CAP) deg = CAP;
    const int* vs = g_slots + node * CAP;
    const uint4* f16 = reinterpret_cast<const uint4*>(g_fts16);

    int i = 0;
    for (; i + 4 <= deg; i += 4) {
        int v0 = vs[i + 0], v1 = vs[i + 1], v2 = vs[i + 2], v3 = vs[i + 3];
        uint4 qa = f16[v0 * 8 + l8];
        uint4 qb = f16[v1 * 8 + l8];
        uint4 qc = f16[v2 * 8 + l8];
        uint4 qd = f16[v3 * 8 + l8];
#define HM(q) do { \
        m0 = __hmax2(m0, *reinterpret_cast<__half2*>(&(q).x)); \
        m1 = __hmax2(m1, *reinterpret_cast<__half2*>(&(q).y)); \
        m2 = __hmax2(m2, *reinterpret_cast<__half2*>(&(q).z)); \
        m3 = __hmax2(m3, *reinterpret_cast<__half2*>(&(q).w)); } while (0)
        HM(qa); HM(qb); HM(qc); HM(qd);
    }
    for (; i < deg; ++i) {
        int v = vs[i];
        uint4 q = f16[v * 8 + l8];
        HM(q);
#undef HM
    }

    uint4 pack;
    pack.x = *reinterpret_cast<unsigned*>(&m0);
    pack.y = *reinterpret_cast<unsigned*>(&m1);
    pack.z = *reinterpret_cast<unsigned*>(&m2);
    pack.w = *reinterpret_cast<unsigned*>(&m3);
    reinterpret_cast<uint4*>(g_agg16)[node * 8 + l8] = pack;
}

// ---------------------------------------------------------------------------
// K3: tensor-core GEMM + L2 norm, with a spill-merge prologue.
// Prologue: thread 0 patches this block's rows of g_agg16 with any spill
// entries (expected none; agg has finished and row ranges are disjoint
// across blocks, so plain RMW is race-free).
// Body: 8 warps, each a 16x64 strip via wmma m16n16k16 (fp16 in, fp32
// accum); A cols 0-63 from g_fts16, 64-127 from g_agg16. fp32 row norm.
// ---------------------------------------------------------------------------
__global__ __launch_bounds__(256) void gemm_tc_kernel(float* __restrict__ out,
                                                      int n) {
    __shared__ float Cs[8 * 16 * 64];   // 32 KB

    int t = threadIdx.x;
    int blockBase = blockIdx.x * M_BLK;

    // Spill prologue (skipped when list empty)
    if (t == 0) {
        int ns = g_nspill;
        if (ns > MAX_SPILL) ns = MAX_SPILL;
        for (int e = 0; e < ns; ++e) {
            int u = g_spill[2 * e];
            if (u >= blockBase && u < blockBase + M_BLK && u < n) {
                int v = g_spill[2 * e + 1];
                __half2 zero = __float2half2_rn(0.f);
                const __half2* src =
                    reinterpret_cast<const __half2*>(g_fts16 + (size_t)v * D);
                __half2* dst =
                    reinterpret_cast<__half2*>(g_agg16 + (size_t)u * D);
                for (int c = 0; c < 32; ++c)
                    dst[c] = __hmax2(dst[c], __hmax2(zero, src[c]));
            }
        }
    }
    __syncthreads();

    int warp = t >> 5;
    int lane = t & 31;
    int row0 = blockBase + warp * 16;

    wmma::fragment<wmma::accumulator, 16, 16, 16, float> c[4];
#pragma unroll
    for (int nn = 0; nn < 4; ++nn) wmma::fill_fragment(c[nn], 0.f);

#pragma unroll
    for (int kc = 0; kc < 8; ++kc) {
        const __half* aptr = (kc < 4)
            ? g_fts16 + (size_t)row0 * D + kc * 16
            : g_agg16 + (size_t)row0 * D + (kc - 4) * 16;
        wmma::fragment<wmma::matrix_a, 16, 16, 16, __half, wmma::row_major> a;
        wmma::load_matrix_sync(a, aptr, D);
#pragma unroll
        for (int nn = 0; nn < 4; ++nn) {
            wmma::fragment<wmma::matrix_b, 16, 16, 16, __half, wmma::row_major> b;
            wmma::load_matrix_sync(b, g_W16 + (size_t)(kc * 16) * D + nn * 16, D);
            wmma::mma_sync(c[nn], a, b, c[nn]);
        }
    }

    float* cs = Cs + warp * 16 * 64;
#pragma unroll
    for (int nn = 0; nn < 4; ++nn)
        wmma::store_matrix_sync(cs + nn * 16, c[nn], 64, wmma::mem_row_major);
    __syncwarp();

    int r = lane >> 1;
    int ch = (lane & 1) * 32;
    const float* rowp = cs + r * 64 + ch;
    float v[32];
    float ss = 0.f;
#pragma unroll
    for (int j = 0; j < 32; ++j) {
        v[j] = rowp[j];
        ss = fmaf(v[j], v[j], ss);
    }
    ss += __shfl_xor_sync(0xffffffffu, ss, 1);
    float rn = rsqrtf(ss);

    int grow = row0 + r;
    if (grow < n) {
        float4* o = reinterpret_cast<float4*>(out + (size_t)grow * D + ch);
#pragma unroll
        for (int j = 0; j < 8; ++j) {
            float4 q;
            q.x = v[4 * j + 0] * rn;
            q.y = v[4 * j + 1] * rn;
            q.z = v[4 * j + 2] * rn;
            q.w = v[4 * j + 3] * rn;
            o[j] = q;
        }
    }
}

// ---------------------------------------------------------------------------
// Launch: 4 kernels. Inputs identified by ELEMENT COUNT.
// ---------------------------------------------------------------------------
extern "C" void kernel_launch(void* const* d_in, const int* in_sizes, int n_in,
                              void* d_out, int out_size) {
    const float* fts = 0;
    const void*  ei  = 0;
    const float* W   = 0;
    int n = MAX_NODES, E = MAX_EDGES;

    for (int i = 0; i < n_in; ++i) {
        if (in_sizes[i] == 6400000)      { fts = (const float*)d_in[i]; n = in_sizes[i] / D; }
        else if (in_sizes[i] == 3200000) { ei  = d_in[i]; E = in_sizes[i] / 2; }
        else if (in_sizes[i] == 8192)    { W   = (const float*)d_in[i]; }
    }
    float* out = (float*)d_out;

    int n16 = n * (D / 16);
    init_kernel<<<(n16 + 255) / 256, 256>>>(fts, W, (const int*)ei, E, n);
    fill_slots_kernel<<<(E + 255) / 256, 256>>>(ei, E, n);
    agg_kernel<<<(n + 31) / 32, 256>>>(n);
    gemm_tc_kernel<<<(n + M_BLK - 1) / M_BLK, 256>>>(out, n);
}

// round 15
// speedup vs baseline: 1.4142x; 1.2959x over previous
#include <cuda_runtime.h>
#include <cuda_fp16.h>
#include <mma.h>

using namespace nvcuda;

#define MAX_NODES 100000
#define MAX_EDGES 1600000
#define D 64
#define MAX_FEAT (MAX_NODES * D)
#define PAD 16384                 // rows past n touched by full wmma tiles
#define CAP 64                    // slots per node; P(Poisson(16) > 64) ~ 1e-20
#define MAX_SPILL 8192
#define M_BLK 128                 // rows per GEMM block (8 warps x 16)

// smem layout for the GEMM (dynamic): W | A-tile (A aliased by C after MMA)
#define SW_STRIDE 72              // 64 + 8 pad halves  -> conflict-free ldmatrix
#define SA_STRIDE 136             // 128 + 8 pad halves -> conflict-free ldmatrix
#define SW_BYTES (128 * SW_STRIDE * 2)          // 18432
#define SA_BYTES (M_BLK * SA_STRIDE * 2)        // 34816
#define SMEM_TOTAL (SW_BYTES + SA_BYTES)        // 53248

// Static scratch (no runtime allocation allowed)
__device__ __align__(16) __half g_fts16[MAX_FEAT + PAD];   // 12.8 MB fp16 fts
__device__ __align__(16) __half g_agg16[MAX_FEAT + PAD];   // 12.8 MB fp16 agg
__device__ __align__(16) __half g_W16[128 * D];            // 16 KB  fp16 W
__device__ int g_slots[MAX_NODES * CAP];                   // 25.6 MB
__device__ int g_deg[MAX_NODES];
__device__ int g_spill[2 * MAX_SPILL];
__device__ int g_nspill;
__device__ int g_is64;

__device__ __forceinline__ uint4 cvt8(const float4* s) {
    float4 a = s[0], b = s[1];
    __half2 h0 = __floats2half2_rn(a.x, a.y);
    __half2 h1 = __floats2half2_rn(a.z, a.w);
    __half2 h2 = __floats2half2_rn(b.x, b.y);
    __half2 h3 = __floats2half2_rn(b.z, b.w);
    uint4 pack;
    pack.x = *reinterpret_cast<unsigned*>(&h0);
    pack.y = *reinterpret_cast<unsigned*>(&h1);
    pack.z = *reinterpret_cast<unsigned*>(&h2);
    pack.w = *reinterpret_cast<unsigned*>(&h3);
    return pack;
}

// ---------------------------------------------------------------------------
// K0: convert fts -> fp16 (16 floats/thread, 4 LDG.128 in flight), W -> fp16,
// zero deg/pad/spill; block 0 detects edge_index dtype (int64 => odd int32
// words all zero; int32 => random ids, 4096 all-zero samples impossible).
// ---------------------------------------------------------------------------
__global__ void init_kernel(const float* __restrict__ fts,
                            const float* __restrict__ W,
                            const int* __restrict__ ei32, int E, int n) {
    int i = blockIdx.x * blockDim.x + threadIdx.x;
    int n16 = n * (D / 16);
    if (i < n16) {
        const float4* s = reinterpret_cast<const float4*>(fts) + i * 4;
        uint4 p0 = cvt8(s);
        uint4 p1 = cvt8(s + 2);
        uint4* d = reinterpret_cast<uint4*>(g_fts16) + i * 2;
        d[0] = p0;
        d[1] = p1;
    }
    if (i < PAD / 16) {
        uint4 z = make_uint4(0u, 0u, 0u, 0u);
        uint4* d0 = reinterpret_cast<uint4*>(g_fts16 + MAX_FEAT) + i * 2;
        uint4* d1 = reinterpret_cast<uint4*>(g_agg16 + MAX_FEAT) + i * 2;
        d0[0] = z; d0[1] = z;
        d1[0] = z; d1[1] = z;
    }
    if (i < 512) {
        const float4* s = reinterpret_cast<const float4*>(W) + i * 4;
        uint4 p0 = cvt8(s);
        uint4 p1 = cvt8(s + 2);
        uint4* d = reinterpret_cast<uint4*>(g_W16) + i * 2;
        d[0] = p0;
        d[1] = p1;
    }
    if (i < n) g_deg[i] = 0;
    if (i == 0) g_nspill = 0;
    if (blockIdx.x == 0) {
        __shared__ int any_nonzero;
        if (threadIdx.x == 0) any_nonzero = 0;
        __syncthreads();
        long long total = 2LL * E;
        long long stride = total / 4096;
        if (stride < 2) stride = 2;
        for (int s = threadIdx.x; s < 4096; s += blockDim.x) {
            long long idx = ((long long)s * stride) | 1;
            if (idx < total && ei32[idx] != 0) any_nonzero = 1;
        }
        __syncthreads();
        if (threadIdx.x == 0) g_is64 = any_nonzero ? 0 : 1;
    }
}

__device__ __forceinline__ void load_edge(const void* ei_raw, int E, int e,
                                          int& u, int& v) {
    if (g_is64) {
        const long long* ei = (const long long*)ei_raw;
        u = (int)ei[e];
        v = (int)ei[E + e];
    } else {
        const int* ei = (const int*)ei_raw;
        u = ei[e];
        v = ei[E + e];
    }
}

// ---------------------------------------------------------------------------
// K1: single-pass bucket fill (CSR without scan).
// ---------------------------------------------------------------------------
__global__ void fill_slots_kernel(const void* __restrict__ ei_raw, int E, int n) {
    int e = blockIdx.x * blockDim.x + threadIdx.x;
    if (e >= E) return;
    int u, v;
    load_edge(ei_raw, E, e, u, v);
    if ((unsigned)u >= (unsigned)n || (unsigned)v >= (unsigned)n) return;
    int idx = atomicAdd(&g_deg[u], 1);
    if (idx < CAP) {
        g_slots[u * CAP + idx] = v;
    } else {
        int p = atomicAdd(&g_nspill, 1);
        if (p < MAX_SPILL) { g_spill[2 * p] = u; g_spill[2 * p + 1] = v; }
    }
}

// ---------------------------------------------------------------------------
// K2: aggregation. 8 threads/node, fp16 __hmax2 register max, unroll x4.
// Init at 0 handles ReLU + empty nodes. Output fp16 for the HMMA GEMM.
// ---------------------------------------------------------------------------
__global__ __launch_bounds__(256) void agg_kernel(int n) {
    int node = blockIdx.x * 32 + (threadIdx.x >> 3);
    int l8 = threadIdx.x & 7;
    if (node >= n) return;

    __half2 m0 = __float2half2_rn(0.f);
    __half2 m1 = m0, m2 = m0, m3 = m0;

    int deg = g_deg[node];
    if (deg > CAP) deg = CAP;
    const int* vs = g_slots + node * CAP;
    const uint4* f16 = reinterpret_cast<const uint4*>(g_fts16);

    int i = 0;
    for (; i + 4 <= deg; i += 4) {
        int v0 = vs[i + 0], v1 = vs[i + 1], v2 = vs[i + 2], v3 = vs[i + 3];
        uint4 qa = f16[v0 * 8 + l8];
        uint4 qb = f16[v1 * 8 + l8];
        uint4 qc = f16[v2 * 8 + l8];
        uint4 qd = f16[v3 * 8 + l8];
#define HM(q) do { \
        m0 = __hmax2(m0, *reinterpret_cast<__half2*>(&(q).x)); \
        m1 = __hmax2(m1, *reinterpret_cast<__half2*>(&(q).y)); \
        m2 = __hmax2(m2, *reinterpret_cast<__half2*>(&(q).z)); \
        m3 = __hmax2(m3, *reinterpret_cast<__half2*>(&(q).w)); } while (0)
        HM(qa); HM(qb); HM(qc); HM(qd);
    }
    for (; i < deg; ++i) {
        int v = vs[i];
        uint4 q = f16[v * 8 + l8];
        HM(q);
#undef HM
    }

    uint4 pack;
    pack.x = *reinterpret_cast<unsigned*>(&m0);
    pack.y = *reinterpret_cast<unsigned*>(&m1);
    pack.z = *reinterpret_cast<unsigned*>(&m2);
    pack.w = *reinterpret_cast<unsigned*>(&m3);
    reinterpret_cast<uint4*>(g_agg16)[node * 8 + l8] = pack;
}

// ---------------------------------------------------------------------------
// K3: tensor-core GEMM + L2 norm, SMEM-staged (R12 profile: global-memory
// load_matrix_sync ran at L1=77% / tensor=4.8% — fragment gathers from
// global are uncoalesced and W was re-fetched 256x per block).
//  - W staged once per block: 128x64 halves = 1024 uint4 (R13 bug: only 512
//    were staged, leaving half of sW uninitialized -> NaN; fixed here)
//  - A tile (128 rows x concat-128) staged coalesced (stride 136)
//  - C staging buffer aliases the A tile (dead after MMAs)
//  - spill prologue: thread 0 patches this block's rows (disjoint; plain RMW)
// ---------------------------------------------------------------------------
extern __shared__ __align__(16) char dynsmem[];

__global__ __launch_bounds__(256) void gemm_tc_kernel(float* __restrict__ out,
                                                      int n) {
    __half* sW = reinterpret_cast<__half*>(dynsmem);                 // 18432 B
    __half* sA = reinterpret_cast<__half*>(dynsmem + SW_BYTES);      // 34816 B
    float*  Cs = reinterpret_cast<float*>(dynsmem + SW_BYTES);       // alias sA

    int t = threadIdx.x;
    int blockBase = blockIdx.x * M_BLK;

    // Spill prologue (list empty in practice)
    if (t == 0) {
        int ns = g_nspill;
        if (ns > MAX_SPILL) ns = MAX_SPILL;
        for (int e = 0; e < ns; ++e) {
            int u = g_spill[2 * e];
            if (u >= blockBase && u < blockBase + M_BLK && u < n) {
                int v = g_spill[2 * e + 1];
                __half2 zero = __float2half2_rn(0.f);
                const __half2* src =
                    reinterpret_cast<const __half2*>(g_fts16 + (size_t)v * D);
                __half2* dst =
                    reinterpret_cast<__half2*>(g_agg16 + (size_t)u * D);
                for (int c = 0; c < 32; ++c)
                    dst[c] = __hmax2(dst[c], __hmax2(zero, src[c]));
            }
        }
    }
    __syncthreads();

    // Stage W: 128x64 halves = 8192 halves = 1024 uint4, 4 per thread
#pragma unroll
    for (int c = 0; c < 4; ++c) {
        int idx = t + c * 256;            // 0..1023
        int row = idx >> 3;               // 0..127
        int col = (idx & 7) * 8;          // 0..56
        uint4 q = reinterpret_cast<const uint4*>(g_W16)[idx];
        *reinterpret_cast<uint4*>(sW + row * SW_STRIDE + col) = q;
    }

    // Stage A: 128 rows x 128 cols (fts | agg) = 2048 uint4, 8 per thread
#pragma unroll
    for (int c = 0; c < 8; ++c) {
        int idx = t + c * 256;            // 0..2047
        int row = idx >> 4;
        int ch = idx & 15;                // 16 uint4 per row: 0-7 fts, 8-15 agg
        size_t grow = (size_t)(blockBase + row);
        uint4 q;
        if (ch < 8)
            q = reinterpret_cast<const uint4*>(g_fts16 + grow * D)[ch];
        else
            q = reinterpret_cast<const uint4*>(g_agg16 + grow * D)[ch - 8];
        *reinterpret_cast<uint4*>(sA + row * SA_STRIDE + ch * 8) = q;
    }
    __syncthreads();

    int warp = t >> 5;
    int lane = t & 31;

    wmma::fragment<wmma::accumulator, 16, 16, 16, float> c[4];
#pragma unroll
    for (int nn = 0; nn < 4; ++nn) wmma::fill_fragment(c[nn], 0.f);

#pragma unroll
    for (int kc = 0; kc < 8; ++kc) {
        wmma::fragment<wmma::matrix_a, 16, 16, 16, __half, wmma::row_major> a;
        wmma::load_matrix_sync(a, sA + (warp * 16) * SA_STRIDE + kc * 16,
                               SA_STRIDE);
#pragma unroll
        for (int nn = 0; nn < 4; ++nn) {
            wmma::fragment<wmma::matrix_b, 16, 16, 16, __half, wmma::row_major> b;
            wmma::load_matrix_sync(b, sW + (kc * 16) * SW_STRIDE + nn * 16,
                                   SW_STRIDE);
            wmma::mma_sync(c[nn], a, b, c[nn]);
        }
    }
    __syncthreads();     // all A reads done before C aliases sA

    float* cs = Cs + warp * 16 * 64;
#pragma unroll
    for (int nn = 0; nn < 4; ++nn)
        wmma::store_matrix_sync(cs + nn * 16, c[nn], 64, wmma::mem_row_major);
    __syncwarp();

    int r = lane >> 1;
    int ch = (lane & 1) * 32;
    const float* rowp = cs + r * 64 + ch;
    float v[32];
    float ss = 0.f;
#pragma unroll
    for (int j = 0; j < 32; ++j) {
        v[j] = rowp[j];
        ss = fmaf(v[j], v[j], ss);
    }
    ss += __shfl_xor_sync(0xffffffffu, ss, 1);
    float rn = rsqrtf(ss);

    int grow = blockBase + warp * 16 + r;
    if (grow < n) {
        float4* o = reinterpret_cast<float4*>(out + (size_t)grow * D + ch);
#pragma unroll
        for (int j = 0; j < 8; ++j) {
            float4 q;
            q.x = v[4 * j + 0] * rn;
            q.y = v[4 * j + 1] * rn;
            q.z = v[4 * j + 2] * rn;
            q.w = v[4 * j + 3] * rn;
            o[j] = q;
        }
    }
}

// ---------------------------------------------------------------------------
// Launch: 4 kernels. Inputs identified by ELEMENT COUNT.
// ---------------------------------------------------------------------------
extern "C" void kernel_launch(void* const* d_in, const int* in_sizes, int n_in,
                              void* d_out, int out_size) {
    const float* fts = 0;
    const void*  ei  = 0;
    const float* W   = 0;
    int n = MAX_NODES, E = MAX_EDGES;

    for (int i = 0; i < n_in; ++i) {
        if (in_sizes[i] == 6400000)      { fts = (const float*)d_in[i]; n = in_sizes[i] / D; }
        else if (in_sizes[i] == 3200000) { ei  = d_in[i]; E = in_sizes[i] / 2; }
        else if (in_sizes[i] == 8192)    { W   = (const float*)d_in[i]; }
    }
    float* out = (float*)d_out;

    static int smem_set = 0;
    if (!smem_set) {
        cudaFuncSetAttribute(gemm_tc_kernel,
                             cudaFuncAttributeMaxDynamicSharedMemorySize,
                             SMEM_TOTAL);
        smem_set = 1;
    }

    int n16 = n * (D / 16);
    init_kernel<<<(n16 + 255) / 256, 256>>>(fts, W, (const int*)ei, E, n);
    fill_slots_kernel<<<(E + 255) / 256, 256>>>(ei, E, n);
    agg_kernel<<<(n + 31) / 32, 256>>>(n);
    gemm_tc_kernel<<<(n + M_BLK - 1) / M_BLK, 256, SMEM_TOTAL>>>(out, n);
}

// round 16
// speedup vs baseline: 1.5828x; 1.1192x over previous
#include <cuda_runtime.h>
#include <cuda_fp16.h>
#include <mma.h>

using namespace nvcuda;

#define MAX_NODES 100000
#define MAX_EDGES 1600000
#define D 64
#define MAX_FEAT (MAX_NODES * D)
#define PAD 16384                 // 256 pad rows for full wmma tiles
#define CAP 64                    // slots per node; P(Poisson(16) > 64) ~ 1e-20
#define MAX_SPILL 8192
#define M_BLK 256                 // rows per GEMM block (8 warps x 32)

// smem layout for the GEMM (dynamic): W | A-tile (A aliased by C after MMA)
#define SW_STRIDE 72              // 64 + 8 pad halves  -> conflict-free ldmatrix
#define SA_STRIDE 136             // 128 + 8 pad halves -> conflict-free ldmatrix
#define SC_STRIDE 68              // C staging stride (64 floats = 32-way conflict!)
#define SW_BYTES (128 * SW_STRIDE * 2)          // 18432
#define SA_BYTES (M_BLK * SA_STRIDE * 2)        // 69632
#define SMEM_TOTAL (SW_BYTES + SA_BYTES)        // 88064

// Static scratch (no runtime allocation allowed)
__device__ __align__(16) __half g_fts16[MAX_FEAT + PAD];   // 12.8 MB fp16 fts
__device__ __align__(16) __half g_agg16[MAX_FEAT + PAD];   // 12.8 MB fp16 agg
__device__ __align__(16) __half g_W16[128 * D];            // 16 KB  fp16 W
__device__ int g_slots[MAX_NODES * CAP];                   // 25.6 MB
__device__ int g_deg[MAX_NODES];
__device__ int g_spill[2 * MAX_SPILL];
__device__ int g_nspill;
__device__ int g_is64;

__device__ __forceinline__ uint4 cvt8(const float4* s) {
    float4 a = s[0], b = s[1];
    __half2 h0 = __floats2half2_rn(a.x, a.y);
    __half2 h1 = __floats2half2_rn(a.z, a.w);
    __half2 h2 = __floats2half2_rn(b.x, b.y);
    __half2 h3 = __floats2half2_rn(b.z, b.w);
    uint4 pack;
    pack.x = *reinterpret_cast<unsigned*>(&h0);
    pack.y = *reinterpret_cast<unsigned*>(&h1);
    pack.z = *reinterpret_cast<unsigned*>(&h2);
    pack.w = *reinterpret_cast<unsigned*>(&h3);
    return pack;
}

// ---------------------------------------------------------------------------
// K0: convert fts -> fp16 (16 floats/thread, 4 LDG.128 in flight), W -> fp16,
// zero deg/pad/spill; block 0 detects edge_index dtype (int64 => odd int32
// words all zero; int32 => random ids, 4096 all-zero samples impossible).
// ---------------------------------------------------------------------------
__global__ void init_kernel(const float* __restrict__ fts,
                            const float* __restrict__ W,
                            const int* __restrict__ ei32, int E, int n) {
    int i = blockIdx.x * blockDim.x + threadIdx.x;
    int n16 = n * (D / 16);
    if (i < n16) {
        const float4* s = reinterpret_cast<const float4*>(fts) + i * 4;
        uint4 p0 = cvt8(s);
        uint4 p1 = cvt8(s + 2);
        uint4* d = reinterpret_cast<uint4*>(g_fts16) + i * 2;
        d[0] = p0;
        d[1] = p1;
    }
    if (i < PAD / 16) {
        uint4 z = make_uint4(0u, 0u, 0u, 0u);
        uint4* d0 = reinterpret_cast<uint4*>(g_fts16 + MAX_FEAT) + i * 2;
        uint4* d1 = reinterpret_cast<uint4*>(g_agg16 + MAX_FEAT) + i * 2;
        d0[0] = z; d0[1] = z;
        d1[0] = z; d1[1] = z;
    }
    if (i < 512) {
        const float4* s = reinterpret_cast<const float4*>(W) + i * 4;
        uint4 p0 = cvt8(s);
        uint4 p1 = cvt8(s + 2);
        uint4* d = reinterpret_cast<uint4*>(g_W16) + i * 2;
        d[0] = p0;
        d[1] = p1;
    }
    if (i < n) g_deg[i] = 0;
    if (i == 0) g_nspill = 0;
    if (blockIdx.x == 0) {
        __shared__ int any_nonzero;
        if (threadIdx.x == 0) any_nonzero = 0;
        __syncthreads();
        long long total = 2LL * E;
        long long stride = total / 4096;
        if (stride < 2) stride = 2;
        for (int s = threadIdx.x; s < 4096; s += blockDim.x) {
            long long idx = ((long long)s * stride) | 1;
            if (idx < total && ei32[idx] != 0) any_nonzero = 1;
        }
        __syncthreads();
        if (threadIdx.x == 0) g_is64 = any_nonzero ? 0 : 1;
    }
}

__device__ __forceinline__ void load_edge(const void* ei_raw, int E, int e,
                                          int& u, int& v) {
    if (g_is64) {
        const long long* ei = (const long long*)ei_raw;
        u = (int)ei[e];
        v = (int)ei[E + e];
    } else {
        const int* ei = (const int*)ei_raw;
        u = ei[e];
        v = ei[E + e];
    }
}

// ---------------------------------------------------------------------------
// K1: single-pass bucket fill (CSR without scan).
// ---------------------------------------------------------------------------
__global__ void fill_slots_kernel(const void* __restrict__ ei_raw, int E, int n) {
    int e = blockIdx.x * blockDim.x + threadIdx.x;
    if (e >= E) return;
    int u, v;
    load_edge(ei_raw, E, e, u, v);
    if ((unsigned)u >= (unsigned)n || (unsigned)v >= (unsigned)n) return;
    int idx = atomicAdd(&g_deg[u], 1);
    if (idx < CAP) {
        g_slots[u * CAP + idx] = v;
    } else {
        int p = atomicAdd(&g_nspill, 1);
        if (p < MAX_SPILL) { g_spill[2 * p] = u; g_spill[2 * p + 1] = v; }
    }
}

// ---------------------------------------------------------------------------
// K2: aggregation. 8 threads/node, fp16 __hmax2 register max, unroll x4.
// Init at 0 handles ReLU + empty nodes. Output fp16 for the HMMA GEMM.
// ---------------------------------------------------------------------------
__global__ __launch_bounds__(256) void agg_kernel(int n) {
    int node = blockIdx.x * 32 + (threadIdx.x >> 3);
    int l8 = threadIdx.x & 7;
    if (node >= n) return;

    __half2 m0 = __float2half2_rn(0.f);
    __half2 m1 = m0, m2 = m0, m3 = m0;

    int deg = g_deg[node];
    if (deg > CAP) deg = CAP;
    const int* vs = g_slots + node * CAP;
    const uint4* f16 = reinterpret_cast<const uint4*>(g_fts16);

    int i = 0;
    for (; i + 4 <= deg; i += 4) {
        int v0 = vs[i + 0], v1 = vs[i + 1], v2 = vs[i + 2], v3 = vs[i + 3];
        uint4 qa = f16[v0 * 8 + l8];
        uint4 qb = f16[v1 * 8 + l8];
        uint4 qc = f16[v2 * 8 + l8];
        uint4 qd = f16[v3 * 8 + l8];
#define HM(q) do { \
        m0 = __hmax2(m0, *reinterpret_cast<__half2*>(&(q).x)); \
        m1 = __hmax2(m1, *reinterpret_cast<__half2*>(&(q).y)); \
        m2 = __hmax2(m2, *reinterpret_cast<__half2*>(&(q).z)); \
        m3 = __hmax2(m3, *reinterpret_cast<__half2*>(&(q).w)); } while (0)
        HM(qa); HM(qb); HM(qc); HM(qd);
    }
    for (; i < deg; ++i) {
        int v = vs[i];
        uint4 q = f16[v * 8 + l8];
        HM(q);
#undef HM
    }

    uint4 pack;
    pack.x = *reinterpret_cast<unsigned*>(&m0);
    pack.y = *reinterpret_cast<unsigned*>(&m1);
    pack.z = *reinterpret_cast<unsigned*>(&m2);
    pack.w = *reinterpret_cast<unsigned*>(&m3);
    reinterpret_cast<uint4*>(g_agg16)[node * 8 + l8] = pack;
}

// ---------------------------------------------------------------------------
// K3: tensor-core GEMM + L2 norm, SMEM-staged, 32x64 warp tiles.
//  R15 profile (16x64 tiles): 33.9us, L1=63%, tensor=8.7% -> LDSM-bound.
//  - 32x64 per warp: 0.75 smem fragment loads per MMA (was 1.25)
//  - C staging stride 68 floats: old stride 64 put every epilogue lane at
//    128B spacing = 32-way bank conflict on every LDS.128
//  - W staged once per 256 rows; C aliases the dead A tile
//  - spill prologue: thread 0 patches this block's rows (disjoint; plain RMW)
// ---------------------------------------------------------------------------
extern __shared__ __align__(16) char dynsmem[];

__global__ __launch_bounds__(256) void gemm_tc_kernel(float* __restrict__ out,
                                                      int n) {
    __half* sW = reinterpret_cast<__half*>(dynsmem);                 // 18432 B
    __half* sA = reinterpret_cast<__half*>(dynsmem + SW_BYTES);      // 69632 B
    float*  Cs = reinterpret_cast<float*>(dynsmem + SW_BYTES);       // alias sA

    int t = threadIdx.x;
    int blockBase = blockIdx.x * M_BLK;

    // Spill prologue (list empty in practice)
    if (t == 0) {
        int ns = g_nspill;
        if (ns > MAX_SPILL) ns = MAX_SPILL;
        for (int e = 0; e < ns; ++e) {
            int u = g_spill[2 * e];
            if (u >= blockBase && u < blockBase + M_BLK && u < n) {
                int v = g_spill[2 * e + 1];
                __half2 zero = __float2half2_rn(0.f);
                const __half2* src =
                    reinterpret_cast<const __half2*>(g_fts16 + (size_t)v * D);
                __half2* dst =
                    reinterpret_cast<__half2*>(g_agg16 + (size_t)u * D);
                for (int c = 0; c < 32; ++c)
                    dst[c] = __hmax2(dst[c], __hmax2(zero, src[c]));
            }
        }
    }
    __syncthreads();

    // Stage W: 128x64 halves = 1024 uint4, 4 per thread
#pragma unroll
    for (int c = 0; c < 4; ++c) {
        int idx = t + c * 256;            // 0..1023
        int row = idx >> 3;               // 0..127
        int col = (idx & 7) * 8;          // 0..56
        uint4 q = reinterpret_cast<const uint4*>(g_W16)[idx];
        *reinterpret_cast<uint4*>(sW + row * SW_STRIDE + col) = q;
    }

    // Stage A: 256 rows x 128 cols (fts | agg) = 4096 uint4, 16 per thread
#pragma unroll
    for (int c = 0; c < 16; ++c) {
        int idx = t + c * 256;            // 0..4095
        int row = idx >> 4;
        int ch = idx & 15;                // 16 uint4 per row: 0-7 fts, 8-15 agg
        size_t grow = (size_t)(blockBase + row);
        uint4 q;
        if (ch < 8)
            q = reinterpret_cast<const uint4*>(g_fts16 + grow * D)[ch];
        else
            q = reinterpret_cast<const uint4*>(g_agg16 + grow * D)[ch - 8];
        *reinterpret_cast<uint4*>(sA + row * SA_STRIDE + ch * 8) = q;
    }
    __syncthreads();

    int warp = t >> 5;
    int lane = t & 31;
    int wrow = warp * 32;                 // this warp's first row in the tile

    wmma::fragment<wmma::accumulator, 16, 16, 16, float> c[2][4];
#pragma unroll
    for (int mi = 0; mi < 2; ++mi)
#pragma unroll
        for (int nn = 0; nn < 4; ++nn) wmma::fill_fragment(c[mi][nn], 0.f);

#pragma unroll
    for (int kc = 0; kc < 8; ++kc) {
        wmma::fragment<wmma::matrix_a, 16, 16, 16, __half, wmma::row_major> a0, a1;
        wmma::load_matrix_sync(a0, sA + wrow * SA_STRIDE + kc * 16, SA_STRIDE);
        wmma::load_matrix_sync(a1, sA + (wrow + 16) * SA_STRIDE + kc * 16,
                               SA_STRIDE);
#pragma unroll
        for (int nn = 0; nn < 4; ++nn) {
            wmma::fragment<wmma::matrix_b, 16, 16, 16, __half, wmma::row_major> b;
            wmma::load_matrix_sync(b, sW + (kc * 16) * SW_STRIDE + nn * 16,
                                   SW_STRIDE);
            wmma::mma_sync(c[0][nn], a0, b, c[0][nn]);
            wmma::mma_sync(c[1][nn], a1, b, c[1][nn]);
        }
    }
    __syncthreads();     // all A reads done before C aliases sA

    float* cs = Cs + warp * 32 * SC_STRIDE;    // 32 rows x 68 floats per warp
#pragma unroll
    for (int mi = 0; mi < 2; ++mi)
#pragma unroll
        for (int nn = 0; nn < 4; ++nn)
            wmma::store_matrix_sync(cs + mi * 16 * SC_STRIDE + nn * 16,
                                    c[mi][nn], SC_STRIDE, wmma::mem_row_major);
    __syncwarp();

#pragma unroll
    for (int half = 0; half < 2; ++half) {
        int r = half * 16 + (lane >> 1);
        int ch = (lane & 1) * 32;
        const float* rowp = cs + r * SC_STRIDE + ch;
        float v[32];
        float ss = 0.f;
#pragma unroll
        for (int j = 0; j < 32; ++j) {
            v[j] = rowp[j];
            ss = fmaf(v[j], v[j], ss);
        }
        ss += __shfl_xor_sync(0xffffffffu, ss, 1);
        float rn = rsqrtf(ss);

        int grow = blockBase + wrow + r;
        if (grow < n) {
            float4* o = reinterpret_cast<float4*>(out + (size_t)grow * D + ch);
#pragma unroll
            for (int j = 0; j < 8; ++j) {
                float4 q;
                q.x = v[4 * j + 0] * rn;
                q.y = v[4 * j + 1] * rn;
                q.z = v[4 * j + 2] * rn;
                q.w = v[4 * j + 3] * rn;
                o[j] = q;
            }
        }
    }
}

// ---------------------------------------------------------------------------
// Launch: 4 kernels. Inputs identified by ELEMENT COUNT.
// ---------------------------------------------------------------------------
extern "C" void kernel_launch(void* const* d_in, const int* in_sizes, int n_in,
                              void* d_out, int out_size) {
    const float* fts = 0;
    const void*  ei  = 0;
    const float* W   = 0;
    int n = MAX_NODES, E = MAX_EDGES;

    for (int i = 0; i < n_in; ++i) {
        if (in_sizes[i] == 6400000)      { fts = (const float*)d_in[i]; n = in_sizes[i] / D; }
        else if (in_sizes[i] == 3200000) { ei  = d_in[i]; E = in_sizes[i] / 2; }
        else if (in_sizes[i] == 8192)    { W   = (const float*)d_in[i]; }
    }
    float* out = (float*)d_out;

    static int smem_set = 0;
    if (!smem_set) {
        cudaFuncSetAttribute(gemm_tc_kernel,
                             cudaFuncAttributeMaxDynamicSharedMemorySize,
                             SMEM_TOTAL);
        smem_set = 1;
    }

    int n16 = n * (D / 16);
    init_kernel<<<(n16 + 255) / 256, 256>>>(fts, W, (const int*)ei, E, n);
    fill_slots_kernel<<<(E + 255) / 256, 256>>>(ei, E, n);
    agg_kernel<<<(n + 31) / 32, 256>>>(n);
    gemm_tc_kernel<<<(n + M_BLK - 1) / M_BLK, 256, SMEM_TOTAL>>>(out, n);
}